// round 12
// baseline (speedup 1.0000x reference)
#include <cuda_runtime.h>
#include <cuda_bf16.h>
#include <cuda_fp16.h>
#include <cstdint>

#define Nn 20000
#define Ee 640000
#define Hh 128
#define Gg 128
#define Cc 2
#define Ll 3
#define BN_EPS 1e-5f

#define RSTRIDE 272
#define A_TILE (64 * RSTRIDE)
#define B_TILE (128 * RSTRIDE)
#define SMEM_DYN (2 * A_TILE + 2 * B_TILE)   // 104448 B -> 2 CTAs/SM

#define EDGE4_BLOCKS ((Ee / 4 + 255) / 256)       // 625
#define WPREP_BLOCKS ((5 * Hh * Hh + 255) / 256)  // 320
#define L1_BLOCKS ((Nn + 127) / 128)              // 157

__device__ __forceinline__ uint32_t smem_u32(const void* p) {
    uint32_t a;
    asm("{ .reg .u64 t; cvta.to.shared.u64 t, %1; cvt.u32.u64 %0, t; }" : "=r"(a) : "l"(p));
    return a;
}

#define LDMATRIX_X4(r0, r1, r2, r3, addr) \
    asm volatile("ldmatrix.sync.aligned.m8n8.x4.shared.b16 {%0,%1,%2,%3}, [%4];" \
                 : "=r"(r0), "=r"(r1), "=r"(r2), "=r"(r3) : "r"(addr))

#define MMA_BF16(d, a, b) \
    asm volatile("mma.sync.aligned.m16n8k16.row.col.f32.bf16.bf16.f32 " \
                 "{%0,%1,%2,%3}, {%4,%5,%6,%7}, {%8,%9}, {%0,%1,%2,%3};" \
                 : "+f"((d)[0]), "+f"((d)[1]), "+f"((d)[2]), "+f"((d)[3]) \
                 : "r"((a)[0]), "r"((a)[1]), "r"((a)[2]), "r"((a)[3]), \
                   "r"((b)[0]), "r"((b)[1]))

#define REDG_U32(p, v) asm volatile("red.global.add.u32 [%0], %1;" :: "l"(p), "r"(v) : "memory")
#define REDG_F32(p, v) asm volatile("red.global.add.f32 [%0], %1;" :: "l"(p), "f"(v) : "memory")

// ---------------- scratch ---------------------------------------------------
__device__ float g_Y[Nn * Hh];
__device__ float g_AGG[Nn * Hh];
__device__ __half g_H16[Nn * Hh];
__device__ float g_colS[Hh];
__device__ float g_colQ[Hh];
__device__ float g_s[Hh];
__device__ float g_t[Hh];
__device__ float g_pool[Gg * Hh];
__device__ float g_cnt[Gg];
__device__ int   g_deg[Nn];
__device__ float g_sx[Nn];
__device__ int   g_rowptr[Nn + 1];
__device__ int   g_cursor[Nn];
__device__ int   g_csrc[Ee];
__device__ float g_u[Hh];
__device__ float g_v[Hh];
__device__ unsigned g_ctr[8];
__device__ __nv_bfloat16 g_Whi[5 * Hh * Hh];
__device__ __nv_bfloat16 g_Wlo[5 * Hh * Hh];

// ---------------- merged: hist (REDG, 4 edges/thr) | wprep | uv-prep --------
__global__ void k_prep_all(const int* __restrict__ ei, const float* __restrict__ x,
                           const float* __restrict__ W1, const float* __restrict__ W2,
                           const float* __restrict__ encW, const float* __restrict__ encb) {
    int b = blockIdx.x;
    int tid = threadIdx.x;
    if (b < EDGE4_BLOCKS) {
        int t = b * 256 + tid;
        if (t < Ee / 4) {
            int4 s4 = ((const int4*)ei)[t];
            int4 d4 = ((const int4*)(ei + Ee))[t];
            float x0 = x[s4.x], x1 = x[s4.y], x2 = x[s4.z], x3 = x[s4.w];
            REDG_U32(&g_deg[d4.x], 1u); REDG_F32(&g_sx[d4.x], x0);
            REDG_U32(&g_deg[d4.y], 1u); REDG_F32(&g_sx[d4.y], x1);
            REDG_U32(&g_deg[d4.z], 1u); REDG_F32(&g_sx[d4.z], x2);
            REDG_U32(&g_deg[d4.w], 1u); REDG_F32(&g_sx[d4.w], x3);
        }
    } else if (b < EDGE4_BLOCKS + WPREP_BLOCKS) {
        int idx = (b - EDGE4_BLOCKS) * 256 + tid;
        if (idx < 5 * Hh * Hh) {
            int m = idx >> 14;
            int rem = idx & 16383;
            int n = rem >> 7;
            int k = rem & 127;
            const float* src;
            switch (m) {
                case 0: src = W2; break;
                case 1: src = W1 + 16384; break;
                case 2: src = W2 + 16384; break;
                case 3: src = W1 + 32768; break;
                default: src = W2 + 32768; break;
            }
            float w = src[k * Hh + n];
            __nv_bfloat16 h = __float2bfloat16_rn(w);
            __nv_bfloat16 lo = __float2bfloat16_rn(w - __bfloat162float(h));
            g_Whi[idx] = h;
            g_Wlo[idx] = lo;
        }
    } else {
        int j = tid;
        if (j < Hh) {
            float u = 0.f, v = 0.f;
#pragma unroll 8
            for (int k = 0; k < Hh; k++) {
                float w = W1[k * Hh + j];
                u = fmaf(encW[k], w, u);
                v = fmaf(encb[k], w, v);
            }
            g_u[j] = u;
            g_v[j] = v;
        }
    }
}

// ---------------- scan ------------------------------------------------------
#define SCAN_CH 20
__global__ void k_scan() {
    __shared__ int sh[1024];
    int t = threadIdx.x;
    int base = t * SCAN_CH;
    int loc[SCAN_CH];
    int s = 0;
#pragma unroll
    for (int i = 0; i < SCAN_CH; i++) {
        int n = base + i;
        int d = (n < Nn) ? g_deg[n] : 0;
        loc[i] = s;
        s += d;
    }
    sh[t] = s;
    __syncthreads();
    for (int off = 1; off < 1024; off <<= 1) {
        int v = (t >= off) ? sh[t - off] : 0;
        __syncthreads();
        sh[t] += v;
        __syncthreads();
    }
    int excl = sh[t] - s;
#pragma unroll
    for (int i = 0; i < SCAN_CH; i++) {
        int n = base + i;
        if (n < Nn) {
            int r = excl + loc[i];
            g_rowptr[n] = r;
            g_cursor[n] = r;
        }
    }
    if (t == 1023) g_rowptr[Nn] = sh[1023];
}

// ---------------- BN finalize tail ------------------------------------------
__device__ __forceinline__ void bn_finalize_tail(int tid, int gridN,
                                                 const float* gamma,
                                                 const float* beta,
                                                 int slot) {
    __threadfence();
    __syncthreads();
    __shared__ int isLast;
    if (tid == 0)
        isLast = (atomicAdd(&g_ctr[slot], 1u) == (unsigned)(gridN - 1)) ? 1 : 0;
    __syncthreads();
    if (isLast && tid < Hh) {
        __threadfence();
        float S = ((volatile float*)g_colS)[tid];
        float Q = ((volatile float*)g_colQ)[tid];
        float inv = 1.0f / (float)Nn;
        float mu = S * inv;
        float var = Q * inv - mu * mu;
        float sc = gamma[tid] * rsqrtf(var + BN_EPS);
        g_s[tid] = sc;
        g_t[tid] = beta[tid] - sc * mu;
        g_colS[tid] = 0.f;
        g_colQ[tid] = 0.f;
    }
}

// ---------------- merged: fill (4 edges/thr) | l1 ---------------------------
__global__ void k_fill_l1(const int* __restrict__ ei,
                          const float* __restrict__ x,
                          const float* __restrict__ b1,
                          const float* __restrict__ eps,
                          const float* __restrict__ gamma,
                          const float* __restrict__ beta) {
    int b = blockIdx.x;
    int tid = threadIdx.x;
    if (b < EDGE4_BLOCKS) {
        int t = b * 256 + tid;
        if (t < Ee / 4) {
            int4 s4 = ((const int4*)ei)[t];
            int4 d4 = ((const int4*)(ei + Ee))[t];
            int p0 = atomicAdd(&g_cursor[d4.x], 1); g_csrc[p0] = s4.x;
            int p1 = atomicAdd(&g_cursor[d4.y], 1); g_csrc[p1] = s4.y;
            int p2 = atomicAdd(&g_cursor[d4.z], 1); g_csrc[p2] = s4.z;
            int p3 = atomicAdd(&g_cursor[d4.w], 1); g_csrc[p3] = s4.w;
        }
        return;
    }
    __shared__ float sa[128];
    __shared__ float sc_[128];
    int bid = b - EDGE4_BLOCKS;
    int i0 = bid * 128;
    int j = tid;
    float e0 = 1.0f + eps[0];
    if (j < 128) {
        int i = i0 + j;
        if (i < Nn) {
            sa[j] = fmaf(e0, x[i], g_sx[i]);
            sc_[j] = e0 + (float)g_deg[i];
        }
    }
    __syncthreads();
    if (j < Hh) {
        float u = g_u[j], v = g_v[j], bb = b1[j];
        float ps = 0.f, pq = 0.f;
        int rmax = min(128, Nn - i0);
#pragma unroll 4
        for (int r = 0; r < rmax; r++) {
            float z = fmaf(sa[r], u, fmaf(sc_[r], v, bb));
            g_Y[(long)(i0 + r) * Hh + j] = z;
            ps += z;
            pq += z * z;
        }
        atomicAdd(&g_colS[j], ps);
        atomicAdd(&g_colQ[j], pq);
    }
    bn_finalize_tail(tid, L1_BLOCKS, gamma, beta, 0);
}

// ---------------- gather: AGG = (1+eps)*h_i + sum h[src],  h=relu(bn(z16)) --
__global__ void k_gather(float* __restrict__ AGG,
                         const float* __restrict__ eps, int l) {
    int warp = (blockIdx.x * blockDim.x + threadIdx.x) >> 5;
    int lane = threadIdx.x & 31;
    if (warp >= Nn) return;
    int i = warp;
    const uint2* H = (const uint2*)g_H16;
    float4 s4 = ((const float4*)g_s)[lane];
    float4 t4 = ((const float4*)g_t)[lane];
    int start = g_rowptr[i];
    int end = g_rowptr[i + 1];
    float4 acc = make_float4(0.f, 0.f, 0.f, 0.f);
    int p = start;
    for (; p + 8 <= end; p += 8) {
        uint2 r[8];
#pragma unroll
        for (int q = 0; q < 8; q++) r[q] = H[g_csrc[p + q] * 32 + lane];
#pragma unroll
        for (int q = 0; q < 8; q++) {
            float2 a = __half22float2(*(__half2*)&r[q].x);
            float2 bvl = __half22float2(*(__half2*)&r[q].y);
            acc.x += fmaxf(fmaf(s4.x, a.x, t4.x), 0.f);
            acc.y += fmaxf(fmaf(s4.y, a.y, t4.y), 0.f);
            acc.z += fmaxf(fmaf(s4.z, bvl.x, t4.z), 0.f);
            acc.w += fmaxf(fmaf(s4.w, bvl.y, t4.w), 0.f);
        }
    }
    for (; p + 4 <= end; p += 4) {
        uint2 r[4];
#pragma unroll
        for (int q = 0; q < 4; q++) r[q] = H[g_csrc[p + q] * 32 + lane];
#pragma unroll
        for (int q = 0; q < 4; q++) {
            float2 a = __half22float2(*(__half2*)&r[q].x);
            float2 bvl = __half22float2(*(__half2*)&r[q].y);
            acc.x += fmaxf(fmaf(s4.x, a.x, t4.x), 0.f);
            acc.y += fmaxf(fmaf(s4.y, a.y, t4.y), 0.f);
            acc.z += fmaxf(fmaf(s4.z, bvl.x, t4.z), 0.f);
            acc.w += fmaxf(fmaf(s4.w, bvl.y, t4.w), 0.f);
        }
    }
    for (; p < end; p++) {
        uint2 r0 = H[g_csrc[p] * 32 + lane];
        float2 a = __half22float2(*(__half2*)&r0.x);
        float2 bvl = __half22float2(*(__half2*)&r0.y);
        acc.x += fmaxf(fmaf(s4.x, a.x, t4.x), 0.f);
        acc.y += fmaxf(fmaf(s4.y, a.y, t4.y), 0.f);
        acc.z += fmaxf(fmaf(s4.z, bvl.x, t4.z), 0.f);
        acc.w += fmaxf(fmaf(s4.w, bvl.y, t4.w), 0.f);
    }
    uint2 ri = H[i * 32 + lane];
    float2 ai = __half22float2(*(__half2*)&ri.x);
    float2 bi = __half22float2(*(__half2*)&ri.y);
    float el = 1.0f + eps[l];
    float4 o;
    o.x = fmaf(el, fmaxf(fmaf(s4.x, ai.x, t4.x), 0.f), acc.x);
    o.y = fmaf(el, fmaxf(fmaf(s4.y, ai.y, t4.y), 0.f), acc.y);
    o.z = fmaf(el, fmaxf(fmaf(s4.z, bi.x, t4.z), 0.f), acc.z);
    o.w = fmaf(el, fmaxf(fmaf(s4.w, bi.y, t4.w), 0.f), acc.w);
    *(float4*)(AGG + (long)i * Hh + lane * 4) = o;
}

// ---------------- tensor-core GEMM (512 thr, 64x128 tile, occ 2 -> 50%) -----
__global__ __launch_bounds__(512, 2) void k_gemm_tc(const float* __restrict__ A,
                                                    int widx,
                                                    const float* __restrict__ bias,
                                                    int usePre,
                                                    float* __restrict__ OutF,
                                                    __half* __restrict__ OutH,
                                                    const float* __restrict__ gamma,
                                                    const float* __restrict__ beta,
                                                    int slot) {
    extern __shared__ __align__(16) char smem[];
    char* Ahi = smem;
    char* Alo = smem + A_TILE;
    char* Bhi = smem + 2 * A_TILE;
    char* Blo = smem + 2 * A_TILE + B_TILE;

    int tid = threadIdx.x;
    int wid = tid >> 5;
    int lane = tid & 31;
    int row0 = blockIdx.x * 64;

    // --- stage B (global latency overlaps A convert) ---
    const __nv_bfloat16* WH = g_Whi + (long)widx * Hh * Hh;
    const __nv_bfloat16* WL = g_Wlo + (long)widx * Hh * Hh;
#pragma unroll
    for (int it = 0; it < 4; it++) {
        int idx = it * 512 + tid;       // 0..2047 uint4 ids
        int n = idx >> 4;
        int k0 = (idx & 15) * 8;
        uint32_t off = (uint32_t)n * RSTRIDE + k0 * 2;
        *(uint4*)(Bhi + off) = *(const uint4*)(WH + n * Hh + k0);
        *(uint4*)(Blo + off) = *(const uint4*)(WL + n * Hh + k0);
    }

    // --- convert A: 64 rows x 128 k ---
#pragma unroll
    for (int it = 0; it < 4; it++) {
        int idx = it * 512 + tid;       // 0..2047 float4 ids
        int row = idx >> 5;
        int c4 = idx & 31;
        int k0 = c4 * 4;
        int gr = row0 + row;
        float4 v = make_float4(0.f, 0.f, 0.f, 0.f);
        if (gr < Nn) {
            v = *(const float4*)(A + (long)gr * Hh + k0);
            if (usePre) {
                float4 s4 = *(const float4*)(g_s + k0);
                float4 t4 = *(const float4*)(g_t + k0);
                v.x = fmaxf(fmaf(s4.x, v.x, t4.x), 0.f);
                v.y = fmaxf(fmaf(s4.y, v.y, t4.y), 0.f);
                v.z = fmaxf(fmaf(s4.z, v.z, t4.z), 0.f);
                v.w = fmaxf(fmaf(s4.w, v.w, t4.w), 0.f);
            }
        }
        __nv_bfloat162 h01 = __floats2bfloat162_rn(v.x, v.y);
        __nv_bfloat162 h23 = __floats2bfloat162_rn(v.z, v.w);
        __nv_bfloat162 l01 = __floats2bfloat162_rn(v.x - __bfloat162float(h01.x),
                                                   v.y - __bfloat162float(h01.y));
        __nv_bfloat162 l23 = __floats2bfloat162_rn(v.z - __bfloat162float(h23.x),
                                                   v.w - __bfloat162float(h23.y));
        uint32_t off = (uint32_t)row * RSTRIDE + k0 * 2;
        *(uint2*)(Ahi + off) = make_uint2(*(uint32_t*)&h01, *(uint32_t*)&h23);
        *(uint2*)(Alo + off) = make_uint2(*(uint32_t*)&l01, *(uint32_t*)&l23);
    }
    __syncthreads();

    // --- warp tiling: 4x4 grid, each warp 16 rows x 32 cols ---
    int wr = wid >> 2;                  // 0..3
    int wc = wid & 3;                   // 0..3
    int mrow0 = wr * 16;
    int ncol0 = wc * 32;

    float acc[4][4];
#pragma unroll
    for (int nb = 0; nb < 4; nb++)
#pragma unroll
        for (int q = 0; q < 4; q++) acc[nb][q] = 0.f;

    uint32_t aBaseH = smem_u32(Ahi);
    uint32_t aBaseL = smem_u32(Alo);
    uint32_t bBaseH = smem_u32(Bhi);
    uint32_t bBaseL = smem_u32(Blo);

    int aRow = mrow0 + (lane & 15);
    int aK = (lane >> 4) * 8;
    int bRow = ncol0 + (lane & 7) + ((lane >> 4) << 3);
    int bK = ((lane >> 3) & 1) * 8;

#pragma unroll
    for (int k0 = 0; k0 < 128; k0 += 16) {
        uint32_t ah[4], al[4];
        uint32_t ao = (uint32_t)aRow * RSTRIDE + (uint32_t)(k0 + aK) * 2;
        LDMATRIX_X4(ah[0], ah[1], ah[2], ah[3], aBaseH + ao);
        LDMATRIX_X4(al[0], al[1], al[2], al[3], aBaseL + ao);
        uint32_t bh[4][2], bl[4][2];
#pragma unroll
        for (int np = 0; np < 2; np++) {
            uint32_t bo = (uint32_t)(bRow + np * 16) * RSTRIDE + (uint32_t)(k0 + bK) * 2;
            uint32_t r0, r1, r2, r3;
            LDMATRIX_X4(r0, r1, r2, r3, bBaseH + bo);
            bh[np * 2][0] = r0; bh[np * 2][1] = r1;
            bh[np * 2 + 1][0] = r2; bh[np * 2 + 1][1] = r3;
            LDMATRIX_X4(r0, r1, r2, r3, bBaseL + bo);
            bl[np * 2][0] = r0; bl[np * 2][1] = r1;
            bl[np * 2 + 1][0] = r2; bl[np * 2 + 1][1] = r3;
        }
#pragma unroll
        for (int nb = 0; nb < 4; nb++) {
            MMA_BF16(acc[nb], ah, bh[nb]);
            MMA_BF16(acc[nb], ah, bl[nb]);
            MMA_BF16(acc[nb], al, bh[nb]);
        }
    }

    // --- epilogue: bias, store, shfl-reduced BN stats ---
    int cbase = ncol0 + (lane & 3) * 2;
    float2 bi[4];
#pragma unroll
    for (int nb = 0; nb < 4; nb++) bi[nb] = *(const float2*)(bias + cbase + nb * 8);

    float psS[4][2], psQ[4][2];
#pragma unroll
    for (int nb = 0; nb < 4; nb++) {
        psS[nb][0] = 0.f; psS[nb][1] = 0.f;
        psQ[nb][0] = 0.f; psQ[nb][1] = 0.f;
    }
#pragma unroll
    for (int h = 0; h < 2; h++) {
        int m = row0 + mrow0 + h * 8 + (lane >> 2);
        if (m < Nn) {
#pragma unroll
            for (int nb = 0; nb < 4; nb++) {
                float v0 = acc[nb][h * 2 + 0] + bi[nb].x;
                float v1 = acc[nb][h * 2 + 1] + bi[nb].y;
                if (OutH) {
                    __half2 hh = __floats2half2_rn(v0, v1);
                    *(uint32_t*)(OutH + (long)m * Hh + cbase + nb * 8) = *(uint32_t*)&hh;
                } else {
                    *(float2*)(OutF + (long)m * Hh + cbase + nb * 8) = make_float2(v0, v1);
                }
                psS[nb][0] += v0; psQ[nb][0] += v0 * v0;
                psS[nb][1] += v1; psQ[nb][1] += v1 * v1;
            }
        }
    }
#pragma unroll
    for (int nb = 0; nb < 4; nb++)
#pragma unroll
        for (int j = 0; j < 2; j++) {
            float s = psS[nb][j], q = psQ[nb][j];
            s += __shfl_xor_sync(0xffffffffu, s, 4);
            q += __shfl_xor_sync(0xffffffffu, q, 4);
            s += __shfl_xor_sync(0xffffffffu, s, 8);
            q += __shfl_xor_sync(0xffffffffu, q, 8);
            s += __shfl_xor_sync(0xffffffffu, s, 16);
            q += __shfl_xor_sync(0xffffffffu, q, 16);
            if ((lane >> 2) == 0) {
                atomicAdd(&g_colS[cbase + nb * 8 + j], s);
                atomicAdd(&g_colQ[cbase + nb * 8 + j], q);
            }
        }
    bn_finalize_tail(tid, gridDim.x, gamma, beta, slot);
}

// ---------------- final: pool(relu(bn(z16))) + classifier + self-clean ------
__global__ void k_postpool(const int* __restrict__ batch,
                           const float* __restrict__ clsW,
                           const float* __restrict__ clsb,
                           float* __restrict__ out) {
    int idx = blockIdx.x * blockDim.x + threadIdx.x;
    int tid = threadIdx.x;
    if (idx < Nn * Hh / 4) {
        int i = idx >> 5;
        int c = idx & 31;
        uint2 r = ((const uint2*)g_H16)[idx];
        float2 f0 = __half22float2(*(__half2*)&r.x);
        float2 f1 = __half22float2(*(__half2*)&r.y);
        float4 s4 = ((const float4*)g_s)[c];
        float4 t4 = ((const float4*)g_t)[c];
        float4 v;
        v.x = fmaxf(fmaf(s4.x, f0.x, t4.x), 0.f);
        v.y = fmaxf(fmaf(s4.y, f0.y, t4.y), 0.f);
        v.z = fmaxf(fmaf(s4.z, f1.x, t4.z), 0.f);
        v.w = fmaxf(fmaf(s4.w, f1.y, t4.w), 0.f);
        int g = batch[i];
        float* p = g_pool + (long)g * Hh + c * 4;
        asm volatile("red.global.add.v4.f32 [%0], {%1,%2,%3,%4};"
                     :: "l"(p), "f"(v.x), "f"(v.y), "f"(v.z), "f"(v.w)
                     : "memory");
        if (c == 0) atomicAdd(&g_cnt[g], 1.0f);
    }
    if (tid < 8) {
        int z = blockIdx.x * 8 + tid;
        if (z < Nn) { g_deg[z] = 0; g_sx[z] = 0.f; }
    }
    __threadfence();
    __syncthreads();
    __shared__ int isLast;
    if (tid == 0)
        isLast = (atomicAdd(&g_ctr[7], 1u) == (unsigned)(gridDim.x - 1)) ? 1 : 0;
    __syncthreads();
    if (isLast) {
        __threadfence();
        if (tid < Gg * Cc) {
            int g = tid >> 1;
            int cc = tid & 1;
            float inv = 1.0f / fmaxf(((volatile float*)g_cnt)[g], 1.0f);
            float acc = clsb[cc];
#pragma unroll 8
            for (int j = 0; j < Hh; j++)
                acc += ((volatile float*)g_pool)[g * Hh + j] * inv * clsW[j * Cc + cc];
            out[g * Cc + cc] = acc;
        }
        __syncthreads();
        for (int q = tid; q < Gg * Hh; q += blockDim.x) g_pool[q] = 0.f;
        if (tid < Gg) g_cnt[tid] = 0.f;
        if (tid < 8) g_ctr[tid] = 0u;
    }
}

// ---------------- launch ----------------------------------------------------
extern "C" void kernel_launch(void* const* d_in, const int* in_sizes, int n_in,
                              void* d_out, int out_size) {
    const float* x    = (const float*)d_in[0];
    const int*   ei   = (const int*)d_in[1];
    const int*   batch= (const int*)d_in[2];
    const float* encW = (const float*)d_in[3];
    const float* encb = (const float*)d_in[4];
    const float* W1   = (const float*)d_in[5];
    const float* b1   = (const float*)d_in[6];
    const float* g1   = (const float*)d_in[7];
    const float* be1  = (const float*)d_in[8];
    const float* W2   = (const float*)d_in[9];
    const float* b2   = (const float*)d_in[10];
    const float* eps  = (const float*)d_in[11];
    const float* bng  = (const float*)d_in[12];
    const float* bnb  = (const float*)d_in[13];
    const float* clsW = (const float*)d_in[14];
    const float* clsb = (const float*)d_in[15];
    float* out = (float*)d_out;

    float *pY = nullptr, *pAGG = nullptr;
    __half* pH = nullptr;
    cudaGetSymbolAddress((void**)&pY, g_Y);
    cudaGetSymbolAddress((void**)&pAGG, g_AGG);
    cudaGetSymbolAddress((void**)&pH, g_H16);

    static int smemSet = 0;
    if (!smemSet) {
        cudaFuncSetAttribute(k_gemm_tc, cudaFuncAttributeMaxDynamicSharedMemorySize, SMEM_DYN);
        smemSet = 1;
    }

    const int elemBlocks = (Nn * Hh / 4) / 256;          // 2500
    const int gemmBlocks = (Nn + 63) / 64;               // 313
    const int gathBlocks = (Nn + 7) / 8;                 // 2500

    k_prep_all<<<EDGE4_BLOCKS + WPREP_BLOCKS + 1, 256>>>(ei, x, W1, W2, encW, encb);
    k_scan<<<1, 1024>>>();
    k_fill_l1<<<EDGE4_BLOCKS + L1_BLOCKS, 256>>>(ei, x, b1, eps, g1, be1);

    k_gemm_tc<<<gemmBlocks, 512, SMEM_DYN>>>(pY, 0, b2, 1, nullptr, pH, bng, bnb, 1);

    for (int l = 1; l < Ll; l++) {
        k_gather<<<gathBlocks, 256>>>(pAGG, eps, l);
        k_gemm_tc<<<gemmBlocks, 512, SMEM_DYN>>>(pAGG, 2 * l - 1, b1 + l * Hh, 0,
                                                 pY, nullptr, g1 + l * Hh, be1 + l * Hh, 2 * l);
        k_gemm_tc<<<gemmBlocks, 512, SMEM_DYN>>>(pY, 2 * l, b2 + l * Hh, 1,
                                                 nullptr, pH, bng + l * Hh, bnb + l * Hh, 2 * l + 1);
    }

    k_postpool<<<elemBlocks, 256>>>(batch, clsW, clsb, out);
}

// round 14
// speedup vs baseline: 1.1874x; 1.1874x over previous
#include <cuda_runtime.h>
#include <cuda_bf16.h>
#include <cuda_fp16.h>
#include <cstdint>

#define Nn 20000
#define Ee 640000
#define Hh 128
#define Gg 128
#define Cc 2
#define Ll 3
#define BN_EPS 1e-5f

#define RSTRIDE 272
#define A_TILE (64 * RSTRIDE)
#define B_TILE (128 * RSTRIDE)
#define SMEM_DYN (2 * A_TILE + 2 * B_TILE)   // 104448 B -> 2 CTAs/SM

#define EDGE4_BLOCKS ((Ee / 4 + 255) / 256)       // 625
#define WPREP_BLOCKS ((5 * Hh * Hh + 255) / 256)  // 320
#define L1_BLOCKS ((Nn + 127) / 128)              // 157

__device__ __forceinline__ uint32_t smem_u32(const void* p) {
    uint32_t a;
    asm("{ .reg .u64 t; cvta.to.shared.u64 t, %1; cvt.u32.u64 %0, t; }" : "=r"(a) : "l"(p));
    return a;
}

#define LDMATRIX_X4(r0, r1, r2, r3, addr) \
    asm volatile("ldmatrix.sync.aligned.m8n8.x4.shared.b16 {%0,%1,%2,%3}, [%4];" \
                 : "=r"(r0), "=r"(r1), "=r"(r2), "=r"(r3) : "r"(addr))

#define MMA_BF16(d, a, b) \
    asm volatile("mma.sync.aligned.m16n8k16.row.col.f32.bf16.bf16.f32 " \
                 "{%0,%1,%2,%3}, {%4,%5,%6,%7}, {%8,%9}, {%0,%1,%2,%3};" \
                 : "+f"((d)[0]), "+f"((d)[1]), "+f"((d)[2]), "+f"((d)[3]) \
                 : "r"((a)[0]), "r"((a)[1]), "r"((a)[2]), "r"((a)[3]), \
                   "r"((b)[0]), "r"((b)[1]))

// ---------------- scratch ---------------------------------------------------
__device__ float g_Y[Nn * Hh];
__device__ float g_AGG[Nn * Hh];
__device__ __half g_H16[Nn * Hh];
__device__ float g_colS[Hh];
__device__ float g_colQ[Hh];
__device__ float g_s[Hh];
__device__ float g_t[Hh];
__device__ float g_pool[Gg * Hh];
__device__ float g_cnt[Gg];
__device__ int   g_deg[Nn];
__device__ float g_sx[Nn];
__device__ int   g_rowptr[Nn + 1];
__device__ int   g_cursor[Nn];
__device__ int   g_csrc[Ee];
__device__ float g_u[Hh];
__device__ float g_v[Hh];
__device__ unsigned g_ctr[8];
__device__ __nv_bfloat16 g_Whi[5 * Hh * Hh];
__device__ __nv_bfloat16 g_Wlo[5 * Hh * Hh];

// ---------------- merged: hist+scan (last block, slot 6) | wprep | uv-prep --
__global__ void k_prep_all(const int* __restrict__ ei, const float* __restrict__ x,
                           const float* __restrict__ W1, const float* __restrict__ W2,
                           const float* __restrict__ encW, const float* __restrict__ encb) {
    int b = blockIdx.x;
    int tid = threadIdx.x;
    if (b < EDGE4_BLOCKS) {
        int t = b * 256 + tid;
        if (t < Ee / 4) {
            int4 s4 = ((const int4*)ei)[t];
            int4 d4 = ((const int4*)(ei + Ee))[t];
            atomicAdd(&g_deg[d4.x], 1); atomicAdd(&g_sx[d4.x], x[s4.x]);
            atomicAdd(&g_deg[d4.y], 1); atomicAdd(&g_sx[d4.y], x[s4.y]);
            atomicAdd(&g_deg[d4.z], 1); atomicAdd(&g_sx[d4.z], x[s4.z]);
            atomicAdd(&g_deg[d4.w], 1); atomicAdd(&g_sx[d4.w], x[s4.w]);
        }
        // last hist block runs the exclusive scan (dedicated counter slot 6)
        __threadfence();
        __syncthreads();
        __shared__ int isLast;
        if (tid == 0)
            isLast = (atomicAdd(&g_ctr[6], 1u) == (unsigned)(EDGE4_BLOCKS - 1)) ? 1 : 0;
        __syncthreads();
        if (isLast) {
            __threadfence();
            __shared__ int sh[256];
            const int CH = (Nn + 255) / 256;    // 79
            int base = tid * CH;
            int s = 0;
            for (int i = 0; i < CH; i++) {
                int n = base + i;
                if (n < Nn) s += g_deg[n];
            }
            sh[tid] = s;
            __syncthreads();
            for (int off = 1; off < 256; off <<= 1) {
                int v = (tid >= off) ? sh[tid - off] : 0;
                __syncthreads();
                sh[tid] += v;
                __syncthreads();
            }
            int run = sh[tid] - s;
            for (int i = 0; i < CH; i++) {
                int n = base + i;
                if (n < Nn) {
                    g_rowptr[n] = run;
                    g_cursor[n] = run;
                    run += g_deg[n];
                }
            }
            if (tid == 255) g_rowptr[Nn] = sh[255];
        }
    } else if (b < EDGE4_BLOCKS + WPREP_BLOCKS) {
        int idx = (b - EDGE4_BLOCKS) * 256 + tid;
        if (idx < 5 * Hh * Hh) {
            int m = idx >> 14;
            int rem = idx & 16383;
            int n = rem >> 7;
            int k = rem & 127;
            const float* src;
            switch (m) {
                case 0: src = W2; break;
                case 1: src = W1 + 16384; break;
                case 2: src = W2 + 16384; break;
                case 3: src = W1 + 32768; break;
                default: src = W2 + 32768; break;
            }
            float w = src[k * Hh + n];
            __nv_bfloat16 h = __float2bfloat16_rn(w);
            __nv_bfloat16 lo = __float2bfloat16_rn(w - __bfloat162float(h));
            g_Whi[idx] = h;
            g_Wlo[idx] = lo;
        }
    } else {
        int j = tid;
        if (j < Hh) {
            float u = 0.f, v = 0.f;
#pragma unroll 8
            for (int k = 0; k < Hh; k++) {
                float w = W1[k * Hh + j];
                u = fmaf(encW[k], w, u);
                v = fmaf(encb[k], w, v);
            }
            g_u[j] = u;
            g_v[j] = v;
        }
    }
}

// ---------------- BN finalize tail ------------------------------------------
__device__ __forceinline__ void bn_finalize_tail(int tid, int gridN,
                                                 const float* gamma,
                                                 const float* beta,
                                                 int slot) {
    __threadfence();
    __syncthreads();
    __shared__ int isLast;
    if (tid == 0)
        isLast = (atomicAdd(&g_ctr[slot], 1u) == (unsigned)(gridN - 1)) ? 1 : 0;
    __syncthreads();
    if (isLast && tid < Hh) {
        __threadfence();
        float S = ((volatile float*)g_colS)[tid];
        float Q = ((volatile float*)g_colQ)[tid];
        float inv = 1.0f / (float)Nn;
        float mu = S * inv;
        float var = Q * inv - mu * mu;
        float sc = gamma[tid] * rsqrtf(var + BN_EPS);
        g_s[tid] = sc;
        g_t[tid] = beta[tid] - sc * mu;
        g_colS[tid] = 0.f;
        g_colQ[tid] = 0.f;
    }
}

// ---------------- merged: fill (4 edges/thr) | l1 ---------------------------
__global__ void k_fill_l1(const int* __restrict__ ei,
                          const float* __restrict__ x,
                          const float* __restrict__ b1,
                          const float* __restrict__ eps,
                          const float* __restrict__ gamma,
                          const float* __restrict__ beta) {
    int b = blockIdx.x;
    int tid = threadIdx.x;
    if (b < EDGE4_BLOCKS) {
        int t = b * 256 + tid;
        if (t < Ee / 4) {
            int4 s4 = ((const int4*)ei)[t];
            int4 d4 = ((const int4*)(ei + Ee))[t];
            int p0 = atomicAdd(&g_cursor[d4.x], 1); g_csrc[p0] = s4.x;
            int p1 = atomicAdd(&g_cursor[d4.y], 1); g_csrc[p1] = s4.y;
            int p2 = atomicAdd(&g_cursor[d4.z], 1); g_csrc[p2] = s4.z;
            int p3 = atomicAdd(&g_cursor[d4.w], 1); g_csrc[p3] = s4.w;
        }
        return;
    }
    __shared__ float sa[128];
    __shared__ float sc_[128];
    int bid = b - EDGE4_BLOCKS;
    int i0 = bid * 128;
    int j = tid;
    float e0 = 1.0f + eps[0];
    if (j < 128) {
        int i = i0 + j;
        if (i < Nn) {
            sa[j] = fmaf(e0, x[i], g_sx[i]);
            sc_[j] = e0 + (float)g_deg[i];
        }
    }
    __syncthreads();
    if (j < Hh) {
        float u = g_u[j], v = g_v[j], bb = b1[j];
        float ps = 0.f, pq = 0.f;
        int rmax = min(128, Nn - i0);
#pragma unroll 4
        for (int r = 0; r < rmax; r++) {
            float z = fmaf(sa[r], u, fmaf(sc_[r], v, bb));
            g_Y[(long)(i0 + r) * Hh + j] = z;
            ps += z;
            pq += z * z;
        }
        atomicAdd(&g_colS[j], ps);
        atomicAdd(&g_colQ[j], pq);
    }
    bn_finalize_tail(tid, L1_BLOCKS, gamma, beta, 0);
}

// ---------------- gather: AGG = (1+eps)*h_i + sum h[src],  h=relu(bn(z16)) --
__global__ void k_gather(float* __restrict__ AGG,
                         const float* __restrict__ eps, int l) {
    int warp = (blockIdx.x * blockDim.x + threadIdx.x) >> 5;
    int lane = threadIdx.x & 31;
    if (warp >= Nn) return;
    int i = warp;
    const uint2* H = (const uint2*)g_H16;
    float4 s4 = ((const float4*)g_s)[lane];
    float4 t4 = ((const float4*)g_t)[lane];
    int start = g_rowptr[i];
    int end = g_rowptr[i + 1];
    float4 acc = make_float4(0.f, 0.f, 0.f, 0.f);
    int p = start;
    for (; p + 8 <= end; p += 8) {
        uint2 r[8];
#pragma unroll
        for (int q = 0; q < 8; q++) r[q] = H[g_csrc[p + q] * 32 + lane];
#pragma unroll
        for (int q = 0; q < 8; q++) {
            float2 a = __half22float2(*(__half2*)&r[q].x);
            float2 bvl = __half22float2(*(__half2*)&r[q].y);
            acc.x += fmaxf(fmaf(s4.x, a.x, t4.x), 0.f);
            acc.y += fmaxf(fmaf(s4.y, a.y, t4.y), 0.f);
            acc.z += fmaxf(fmaf(s4.z, bvl.x, t4.z), 0.f);
            acc.w += fmaxf(fmaf(s4.w, bvl.y, t4.w), 0.f);
        }
    }
    for (; p + 4 <= end; p += 4) {
        uint2 r[4];
#pragma unroll
        for (int q = 0; q < 4; q++) r[q] = H[g_csrc[p + q] * 32 + lane];
#pragma unroll
        for (int q = 0; q < 4; q++) {
            float2 a = __half22float2(*(__half2*)&r[q].x);
            float2 bvl = __half22float2(*(__half2*)&r[q].y);
            acc.x += fmaxf(fmaf(s4.x, a.x, t4.x), 0.f);
            acc.y += fmaxf(fmaf(s4.y, a.y, t4.y), 0.f);
            acc.z += fmaxf(fmaf(s4.z, bvl.x, t4.z), 0.f);
            acc.w += fmaxf(fmaf(s4.w, bvl.y, t4.w), 0.f);
        }
    }
    for (; p < end; p++) {
        uint2 r0 = H[g_csrc[p] * 32 + lane];
        float2 a = __half22float2(*(__half2*)&r0.x);
        float2 bvl = __half22float2(*(__half2*)&r0.y);
        acc.x += fmaxf(fmaf(s4.x, a.x, t4.x), 0.f);
        acc.y += fmaxf(fmaf(s4.y, a.y, t4.y), 0.f);
        acc.z += fmaxf(fmaf(s4.z, bvl.x, t4.z), 0.f);
        acc.w += fmaxf(fmaf(s4.w, bvl.y, t4.w), 0.f);
    }
    uint2 ri = H[i * 32 + lane];
    float2 ai = __half22float2(*(__half2*)&ri.x);
    float2 bi = __half22float2(*(__half2*)&ri.y);
    float el = 1.0f + eps[l];
    float4 o;
    o.x = fmaf(el, fmaxf(fmaf(s4.x, ai.x, t4.x), 0.f), acc.x);
    o.y = fmaf(el, fmaxf(fmaf(s4.y, ai.y, t4.y), 0.f), acc.y);
    o.z = fmaf(el, fmaxf(fmaf(s4.z, bi.x, t4.z), 0.f), acc.z);
    o.w = fmaf(el, fmaxf(fmaf(s4.w, bi.y, t4.w), 0.f), acc.w);
    *(float4*)(AGG + (long)i * Hh + lane * 4) = o;
}

// ---------------- tensor-core GEMM (R11 shape: 256 thr, 8 warps 32x32) ------
__global__ __launch_bounds__(256, 2) void k_gemm_tc(const float* __restrict__ A,
                                                    int widx,
                                                    const float* __restrict__ bias,
                                                    int usePre,
                                                    float* __restrict__ OutF,
                                                    __half* __restrict__ OutH,
                                                    const float* __restrict__ gamma,
                                                    const float* __restrict__ beta,
                                                    int slot) {
    extern __shared__ __align__(16) char smem[];
    char* Ahi = smem;
    char* Alo = smem + A_TILE;
    char* Bhi = smem + 2 * A_TILE;
    char* Blo = smem + 2 * A_TILE + B_TILE;

    int tid = threadIdx.x;
    int wid = tid >> 5;
    int lane = tid & 31;
    int row0 = blockIdx.x * 64;

    const __nv_bfloat16* WH = g_Whi + (long)widx * Hh * Hh;
    const __nv_bfloat16* WL = g_Wlo + (long)widx * Hh * Hh;
#pragma unroll
    for (int it = 0; it < 8; it++) {
        int idx = it * 256 + tid;
        int n = idx >> 4;
        int k0 = (idx & 15) * 8;
        uint32_t off = (uint32_t)n * RSTRIDE + k0 * 2;
        *(uint4*)(Bhi + off) = *(const uint4*)(WH + n * Hh + k0);
        *(uint4*)(Blo + off) = *(const uint4*)(WL + n * Hh + k0);
    }

#pragma unroll
    for (int it = 0; it < 8; it++) {
        int idx = it * 256 + tid;
        int row = idx >> 5;
        int c4 = idx & 31;
        int k0 = c4 * 4;
        int gr = row0 + row;
        float4 v = make_float4(0.f, 0.f, 0.f, 0.f);
        if (gr < Nn) {
            v = *(const float4*)(A + (long)gr * Hh + k0);
            if (usePre) {
                float4 s4 = *(const float4*)(g_s + k0);
                float4 t4 = *(const float4*)(g_t + k0);
                v.x = fmaxf(fmaf(s4.x, v.x, t4.x), 0.f);
                v.y = fmaxf(fmaf(s4.y, v.y, t4.y), 0.f);
                v.z = fmaxf(fmaf(s4.z, v.z, t4.z), 0.f);
                v.w = fmaxf(fmaf(s4.w, v.w, t4.w), 0.f);
            }
        }
        __nv_bfloat162 h01 = __floats2bfloat162_rn(v.x, v.y);
        __nv_bfloat162 h23 = __floats2bfloat162_rn(v.z, v.w);
        __nv_bfloat162 l01 = __floats2bfloat162_rn(v.x - __bfloat162float(h01.x),
                                                   v.y - __bfloat162float(h01.y));
        __nv_bfloat162 l23 = __floats2bfloat162_rn(v.z - __bfloat162float(h23.x),
                                                   v.w - __bfloat162float(h23.y));
        uint32_t off = (uint32_t)row * RSTRIDE + k0 * 2;
        *(uint2*)(Ahi + off) = make_uint2(*(uint32_t*)&h01, *(uint32_t*)&h23);
        *(uint2*)(Alo + off) = make_uint2(*(uint32_t*)&l01, *(uint32_t*)&l23);
    }
    __syncthreads();

    int wr = wid >> 2;
    int wc = wid & 3;
    int mrow0 = wr * 32;
    int ncol0 = wc * 32;

    float acc[2][4][4];
#pragma unroll
    for (int mb = 0; mb < 2; mb++)
#pragma unroll
        for (int nb = 0; nb < 4; nb++)
#pragma unroll
            for (int q = 0; q < 4; q++) acc[mb][nb][q] = 0.f;

    uint32_t aBaseH = smem_u32(Ahi);
    uint32_t aBaseL = smem_u32(Alo);
    uint32_t bBaseH = smem_u32(Bhi);
    uint32_t bBaseL = smem_u32(Blo);

    int aRow = mrow0 + (lane & 15);
    int aK = (lane >> 4) * 8;
    int bRow = ncol0 + (lane & 7) + ((lane >> 4) << 3);
    int bK = ((lane >> 3) & 1) * 8;

#pragma unroll
    for (int k0 = 0; k0 < 128; k0 += 16) {
        uint32_t ah[2][4], al[2][4];
#pragma unroll
        for (int mb = 0; mb < 2; mb++) {
            uint32_t ao = (uint32_t)(aRow + mb * 16) * RSTRIDE + (uint32_t)(k0 + aK) * 2;
            LDMATRIX_X4(ah[mb][0], ah[mb][1], ah[mb][2], ah[mb][3], aBaseH + ao);
            LDMATRIX_X4(al[mb][0], al[mb][1], al[mb][2], al[mb][3], aBaseL + ao);
        }
        uint32_t bh[4][2], bl[4][2];
#pragma unroll
        for (int np = 0; np < 2; np++) {
            uint32_t bo = (uint32_t)(bRow + np * 16) * RSTRIDE + (uint32_t)(k0 + bK) * 2;
            uint32_t r0, r1, r2, r3;
            LDMATRIX_X4(r0, r1, r2, r3, bBaseH + bo);
            bh[np * 2][0] = r0; bh[np * 2][1] = r1;
            bh[np * 2 + 1][0] = r2; bh[np * 2 + 1][1] = r3;
            LDMATRIX_X4(r0, r1, r2, r3, bBaseL + bo);
            bl[np * 2][0] = r0; bl[np * 2][1] = r1;
            bl[np * 2 + 1][0] = r2; bl[np * 2 + 1][1] = r3;
        }
#pragma unroll
        for (int mb = 0; mb < 2; mb++)
#pragma unroll
            for (int nb = 0; nb < 4; nb++) {
                MMA_BF16(acc[mb][nb], ah[mb], bh[nb]);
                MMA_BF16(acc[mb][nb], ah[mb], bl[nb]);
                MMA_BF16(acc[mb][nb], al[mb], bh[nb]);
            }
    }

    int cbase = ncol0 + (lane & 3) * 2;
    float2 bi[4];
#pragma unroll
    for (int nb = 0; nb < 4; nb++) bi[nb] = *(const float2*)(bias + cbase + nb * 8);

    float psS[4][2], psQ[4][2];
#pragma unroll
    for (int nb = 0; nb < 4; nb++) {
        psS[nb][0] = 0.f; psS[nb][1] = 0.f;
        psQ[nb][0] = 0.f; psQ[nb][1] = 0.f;
    }
#pragma unroll
    for (int mb = 0; mb < 2; mb++)
#pragma unroll
        for (int h = 0; h < 2; h++) {
            int m = row0 + mrow0 + mb * 16 + h * 8 + (lane >> 2);
            if (m < Nn) {
#pragma unroll
                for (int nb = 0; nb < 4; nb++) {
                    float v0 = acc[mb][nb][h * 2 + 0] + bi[nb].x;
                    float v1 = acc[mb][nb][h * 2 + 1] + bi[nb].y;
                    if (OutH) {
                        __half2 hh = __floats2half2_rn(v0, v1);
                        *(uint32_t*)(OutH + (long)m * Hh + cbase + nb * 8) = *(uint32_t*)&hh;
                    } else {
                        *(float2*)(OutF + (long)m * Hh + cbase + nb * 8) = make_float2(v0, v1);
                    }
                    psS[nb][0] += v0; psQ[nb][0] += v0 * v0;
                    psS[nb][1] += v1; psQ[nb][1] += v1 * v1;
                }
            }
        }
#pragma unroll
    for (int nb = 0; nb < 4; nb++)
#pragma unroll
        for (int j = 0; j < 2; j++) {
            float s = psS[nb][j], q = psQ[nb][j];
            s += __shfl_xor_sync(0xffffffffu, s, 4);
            q += __shfl_xor_sync(0xffffffffu, q, 4);
            s += __shfl_xor_sync(0xffffffffu, s, 8);
            q += __shfl_xor_sync(0xffffffffu, q, 8);
            s += __shfl_xor_sync(0xffffffffu, s, 16);
            q += __shfl_xor_sync(0xffffffffu, q, 16);
            if ((lane >> 2) == 0) {
                atomicAdd(&g_colS[cbase + nb * 8 + j], s);
                atomicAdd(&g_colQ[cbase + nb * 8 + j], q);
            }
        }
    bn_finalize_tail(tid, gridDim.x, gamma, beta, slot);
}

// ---------------- final: pool(relu(bn(z16))) + classifier + self-clean ------
__global__ void k_postpool(const int* __restrict__ batch,
                           const float* __restrict__ clsW,
                           const float* __restrict__ clsb,
                           float* __restrict__ out) {
    int idx = blockIdx.x * blockDim.x + threadIdx.x;
    int tid = threadIdx.x;
    if (idx < Nn * Hh / 4) {
        int i = idx >> 5;
        int c = idx & 31;
        uint2 r = ((const uint2*)g_H16)[idx];
        float2 f0 = __half22float2(*(__half2*)&r.x);
        float2 f1 = __half22float2(*(__half2*)&r.y);
        float4 s4 = ((const float4*)g_s)[c];
        float4 t4 = ((const float4*)g_t)[c];
        float4 v;
        v.x = fmaxf(fmaf(s4.x, f0.x, t4.x), 0.f);
        v.y = fmaxf(fmaf(s4.y, f0.y, t4.y), 0.f);
        v.z = fmaxf(fmaf(s4.z, f1.x, t4.z), 0.f);
        v.w = fmaxf(fmaf(s4.w, f1.y, t4.w), 0.f);
        int g = batch[i];
        float* p = g_pool + (long)g * Hh + c * 4;
        asm volatile("red.global.add.v4.f32 [%0], {%1,%2,%3,%4};"
                     :: "l"(p), "f"(v.x), "f"(v.y), "f"(v.z), "f"(v.w)
                     : "memory");
        if (c == 0) atomicAdd(&g_cnt[g], 1.0f);
    }
    if (tid < 8) {
        int z = blockIdx.x * 8 + tid;
        if (z < Nn) { g_deg[z] = 0; g_sx[z] = 0.f; }
    }
    __threadfence();
    __syncthreads();
    __shared__ int isLast;
    if (tid == 0)
        isLast = (atomicAdd(&g_ctr[7], 1u) == (unsigned)(gridDim.x - 1)) ? 1 : 0;
    __syncthreads();
    if (isLast) {
        __threadfence();
        if (tid < Gg * Cc) {
            int g = tid >> 1;
            int cc = tid & 1;
            float inv = 1.0f / fmaxf(((volatile float*)g_cnt)[g], 1.0f);
            float acc = clsb[cc];
#pragma unroll 8
            for (int j = 0; j < Hh; j++)
                acc += ((volatile float*)g_pool)[g * Hh + j] * inv * clsW[j * Cc + cc];
            out[g * Cc + cc] = acc;
        }
        __syncthreads();
        for (int q = tid; q < Gg * Hh; q += blockDim.x) g_pool[q] = 0.f;
        if (tid < Gg) g_cnt[tid] = 0.f;
        if (tid < 8) g_ctr[tid] = 0u;
    }
}

// ---------------- launch ----------------------------------------------------
extern "C" void kernel_launch(void* const* d_in, const int* in_sizes, int n_in,
                              void* d_out, int out_size) {
    const float* x    = (const float*)d_in[0];
    const int*   ei   = (const int*)d_in[1];
    const int*   batch= (const int*)d_in[2];
    const float* encW = (const float*)d_in[3];
    const float* encb = (const float*)d_in[4];
    const float* W1   = (const float*)d_in[5];
    const float* b1   = (const float*)d_in[6];
    const float* g1   = (const float*)d_in[7];
    const float* be1  = (const float*)d_in[8];
    const float* W2   = (const float*)d_in[9];
    const float* b2   = (const float*)d_in[10];
    const float* eps  = (const float*)d_in[11];
    const float* bng  = (const float*)d_in[12];
    const float* bnb  = (const float*)d_in[13];
    const float* clsW = (const float*)d_in[14];
    const float* clsb = (const float*)d_in[15];
    float* out = (float*)d_out;

    float *pY = nullptr, *pAGG = nullptr;
    __half* pH = nullptr;
    cudaGetSymbolAddress((void**)&pY, g_Y);
    cudaGetSymbolAddress((void**)&pAGG, g_AGG);
    cudaGetSymbolAddress((void**)&pH, g_H16);

    static int smemSet = 0;
    if (!smemSet) {
        cudaFuncSetAttribute(k_gemm_tc, cudaFuncAttributeMaxDynamicSharedMemorySize, SMEM_DYN);
        smemSet = 1;
    }

    const int elemBlocks = (Nn * Hh / 4) / 256;          // 2500
    const int gemmBlocks = (Nn + 63) / 64;               // 313
    const int gathBlocks = (Nn + 7) / 8;                 // 2500

    k_prep_all<<<EDGE4_BLOCKS + WPREP_BLOCKS + 1, 256>>>(ei, x, W1, W2, encW, encb);
    k_fill_l1<<<EDGE4_BLOCKS + L1_BLOCKS, 256>>>(ei, x, b1, eps, g1, be1);

    k_gemm_tc<<<gemmBlocks, 256, SMEM_DYN>>>(pY, 0, b2, 1, nullptr, pH, bng, bnb, 1);

    for (int l = 1; l < Ll; l++) {
        k_gather<<<gathBlocks, 256>>>(pAGG, eps, l);
        k_gemm_tc<<<gemmBlocks, 256, SMEM_DYN>>>(pAGG, 2 * l - 1, b1 + l * Hh, 0,
                                                 pY, nullptr, g1 + l * Hh, be1 + l * Hh, 2 * l);
        k_gemm_tc<<<gemmBlocks, 256, SMEM_DYN>>>(pY, 2 * l, b2 + l * Hh, 1,
                                                 nullptr, pH, bng + l * Hh, bnb + l * Hh, 2 * l + 1);
    }

    k_postpool<<<elemBlocks, 256>>>(batch, clsW, clsb, out);
}

// round 15
// speedup vs baseline: 1.2701x; 1.0696x over previous
#include <cuda_runtime.h>
#include <cuda_bf16.h>
#include <cuda_fp16.h>
#include <cstdint>

#define Nn 20000
#define Ee 640000
#define Hh 128
#define Gg 128
#define Cc 2
#define Ll 3
#define BN_EPS 1e-5f

#define RSTRIDE 272
#define A_TILE (64 * RSTRIDE)
#define B_TILE (128 * RSTRIDE)
#define SMEM_DYN (2 * A_TILE + 2 * B_TILE)   // 104448 B -> 2 CTAs/SM

#define EDGE4_BLOCKS ((Ee / 4 + 255) / 256)       // 625
#define WPREP_BLOCKS ((5 * Hh * Hh + 255) / 256)  // 320
#define L1_BLOCKS ((Nn + 127) / 128)              // 157

__device__ __forceinline__ uint32_t smem_u32(const void* p) {
    uint32_t a;
    asm("{ .reg .u64 t; cvta.to.shared.u64 t, %1; cvt.u32.u64 %0, t; }" : "=r"(a) : "l"(p));
    return a;
}

#define LDMATRIX_X4(r0, r1, r2, r3, addr) \
    asm volatile("ldmatrix.sync.aligned.m8n8.x4.shared.b16 {%0,%1,%2,%3}, [%4];" \
                 : "=r"(r0), "=r"(r1), "=r"(r2), "=r"(r3) : "r"(addr))

#define MMA_BF16(d, a, b) \
    asm volatile("mma.sync.aligned.m16n8k16.row.col.f32.bf16.bf16.f32 " \
                 "{%0,%1,%2,%3}, {%4,%5,%6,%7}, {%8,%9}, {%0,%1,%2,%3};" \
                 : "+f"((d)[0]), "+f"((d)[1]), "+f"((d)[2]), "+f"((d)[3]) \
                 : "r"((a)[0]), "r"((a)[1]), "r"((a)[2]), "r"((a)[3]), \
                   "r"((b)[0]), "r"((b)[1]))

// ---------------- scratch ---------------------------------------------------
__device__ float g_Y[Nn * Hh];       // gemm1 output (fp32)
__device__ float g_AGG[Nn * Hh];     // gather output / gemm2 raw-Z scratch (fp32)
__device__ __half g_H16[Nn * Hh];    // gather operand: activated h (mid) / raw z (last)
__device__ float g_colS[Hh];
__device__ float g_colQ[Hh];
__device__ float g_s[Hh];
__device__ float g_t[Hh];
__device__ float g_pool[Gg * Hh];
__device__ float g_cnt[Gg];
__device__ int   g_deg[Nn];
__device__ float g_sx[Nn];
__device__ int   g_rowptr[Nn + 1];
__device__ int   g_cursor[Nn];
__device__ int   g_csrc[Ee];
__device__ float g_u[Hh];
__device__ float g_v[Hh];
__device__ unsigned g_ctr[8];
__device__ __nv_bfloat16 g_Whi[5 * Hh * Hh];
__device__ __nv_bfloat16 g_Wlo[5 * Hh * Hh];

// ---------------- merged: hist (4 edges/thr) | wprep | uv-prep --------------
__global__ void k_prep_all(const int* __restrict__ ei, const float* __restrict__ x,
                           const float* __restrict__ W1, const float* __restrict__ W2,
                           const float* __restrict__ encW, const float* __restrict__ encb) {
    int b = blockIdx.x;
    int tid = threadIdx.x;
    if (b < EDGE4_BLOCKS) {
        int t = b * 256 + tid;
        if (t < Ee / 4) {
            int4 s4 = ((const int4*)ei)[t];
            int4 d4 = ((const int4*)(ei + Ee))[t];
            atomicAdd(&g_deg[d4.x], 1); atomicAdd(&g_sx[d4.x], x[s4.x]);
            atomicAdd(&g_deg[d4.y], 1); atomicAdd(&g_sx[d4.y], x[s4.y]);
            atomicAdd(&g_deg[d4.z], 1); atomicAdd(&g_sx[d4.z], x[s4.z]);
            atomicAdd(&g_deg[d4.w], 1); atomicAdd(&g_sx[d4.w], x[s4.w]);
        }
    } else if (b < EDGE4_BLOCKS + WPREP_BLOCKS) {
        int idx = (b - EDGE4_BLOCKS) * 256 + tid;
        if (idx < 5 * Hh * Hh) {
            int m = idx >> 14;
            int rem = idx & 16383;
            int n = rem >> 7;
            int k = rem & 127;
            const float* src;
            switch (m) {
                case 0: src = W2; break;
                case 1: src = W1 + 16384; break;
                case 2: src = W2 + 16384; break;
                case 3: src = W1 + 32768; break;
                default: src = W2 + 32768; break;
            }
            float w = src[k * Hh + n];
            __nv_bfloat16 h = __float2bfloat16_rn(w);
            __nv_bfloat16 lo = __float2bfloat16_rn(w - __bfloat162float(h));
            g_Whi[idx] = h;
            g_Wlo[idx] = lo;
        }
    } else {
        int j = tid;
        if (j < Hh) {
            float u = 0.f, v = 0.f;
#pragma unroll 8
            for (int k = 0; k < Hh; k++) {
                float w = W1[k * Hh + j];
                u = fmaf(encW[k], w, u);
                v = fmaf(encb[k], w, v);
            }
            g_u[j] = u;
            g_v[j] = v;
        }
    }
}

// ---------------- scan (1024 threads, dedicated) ----------------------------
#define SCAN_CH 20
__global__ void k_scan() {
    __shared__ int sh[1024];
    int t = threadIdx.x;
    int base = t * SCAN_CH;
    int loc[SCAN_CH];
    int s = 0;
#pragma unroll
    for (int i = 0; i < SCAN_CH; i++) {
        int n = base + i;
        int d = (n < Nn) ? g_deg[n] : 0;
        loc[i] = s;
        s += d;
    }
    sh[t] = s;
    __syncthreads();
    for (int off = 1; off < 1024; off <<= 1) {
        int v = (t >= off) ? sh[t - off] : 0;
        __syncthreads();
        sh[t] += v;
        __syncthreads();
    }
    int excl = sh[t] - s;
#pragma unroll
    for (int i = 0; i < SCAN_CH; i++) {
        int n = base + i;
        if (n < Nn) {
            int r = excl + loc[i];
            g_rowptr[n] = r;
            g_cursor[n] = r;
        }
    }
    if (t == 1023) g_rowptr[Nn] = sh[1023];
}

// ---------------- BN finalize tail ------------------------------------------
__device__ __forceinline__ void bn_finalize_tail(int tid, int gridN,
                                                 const float* gamma,
                                                 const float* beta,
                                                 int slot) {
    __threadfence();
    __syncthreads();
    __shared__ int isLast;
    if (tid == 0)
        isLast = (atomicAdd(&g_ctr[slot], 1u) == (unsigned)(gridN - 1)) ? 1 : 0;
    __syncthreads();
    if (isLast && tid < Hh) {
        __threadfence();
        float S = ((volatile float*)g_colS)[tid];
        float Q = ((volatile float*)g_colQ)[tid];
        float inv = 1.0f / (float)Nn;
        float mu = S * inv;
        float var = Q * inv - mu * mu;
        float sc = gamma[tid] * rsqrtf(var + BN_EPS);
        g_s[tid] = sc;
        g_t[tid] = beta[tid] - sc * mu;
        g_colS[tid] = 0.f;
        g_colQ[tid] = 0.f;
    }
}

// ---------------- merged: fill (4 edges/thr) | l1 ---------------------------
__global__ void k_fill_l1(const int* __restrict__ ei,
                          const float* __restrict__ x,
                          const float* __restrict__ b1,
                          const float* __restrict__ eps,
                          const float* __restrict__ gamma,
                          const float* __restrict__ beta) {
    int b = blockIdx.x;
    int tid = threadIdx.x;
    if (b < EDGE4_BLOCKS) {
        int t = b * 256 + tid;
        if (t < Ee / 4) {
            int4 s4 = ((const int4*)ei)[t];
            int4 d4 = ((const int4*)(ei + Ee))[t];
            int p0 = atomicAdd(&g_cursor[d4.x], 1); g_csrc[p0] = s4.x;
            int p1 = atomicAdd(&g_cursor[d4.y], 1); g_csrc[p1] = s4.y;
            int p2 = atomicAdd(&g_cursor[d4.z], 1); g_csrc[p2] = s4.z;
            int p3 = atomicAdd(&g_cursor[d4.w], 1); g_csrc[p3] = s4.w;
        }
        return;
    }
    __shared__ float sa[128];
    __shared__ float sc_[128];
    int bid = b - EDGE4_BLOCKS;
    int i0 = bid * 128;
    int j = tid;
    float e0 = 1.0f + eps[0];
    if (j < 128) {
        int i = i0 + j;
        if (i < Nn) {
            sa[j] = fmaf(e0, x[i], g_sx[i]);
            sc_[j] = e0 + (float)g_deg[i];
        }
    }
    __syncthreads();
    if (j < Hh) {
        float u = g_u[j], v = g_v[j], bb = b1[j];
        float ps = 0.f, pq = 0.f;
        int rmax = min(128, Nn - i0);
#pragma unroll 4
        for (int r = 0; r < rmax; r++) {
            float z = fmaf(sa[r], u, fmaf(sc_[r], v, bb));
            g_Y[(long)(i0 + r) * Hh + j] = z;
            ps += z;
            pq += z * z;
        }
        atomicAdd(&g_colS[j], ps);
        atomicAdd(&g_colQ[j], pq);
    }
    bn_finalize_tail(tid, L1_BLOCKS, gamma, beta, 0);
}

// ---------------- tohalf: H16 = fp16( relu(bn(Z)) ) -------------------------
__global__ void k_tohalf(const float* __restrict__ Z) {
    int idx = blockIdx.x * blockDim.x + threadIdx.x;   // float4 id
    if (idx >= Nn * Hh / 4) return;
    int c = idx & 31;
    float4 z = ((const float4*)Z)[idx];
    float4 s4 = ((const float4*)g_s)[c];
    float4 t4 = ((const float4*)g_t)[c];
    float vx = fmaxf(fmaf(s4.x, z.x, t4.x), 0.f);
    float vy = fmaxf(fmaf(s4.y, z.y, t4.y), 0.f);
    float vz = fmaxf(fmaf(s4.z, z.z, t4.z), 0.f);
    float vw = fmaxf(fmaf(s4.w, z.w, t4.w), 0.f);
    __half2 h0 = __floats2half2_rn(vx, vy);
    __half2 h1 = __floats2half2_rn(vz, vw);
    ((uint2*)g_H16)[idx] = make_uint2(*(uint32_t*)&h0, *(uint32_t*)&h1);
}

// ---------------- gather (pure adds): AGG = (1+eps)*h_i + sum h[src] --------
__global__ void k_gather(float* __restrict__ AGG,
                         const float* __restrict__ eps, int l) {
    int warp = (blockIdx.x * blockDim.x + threadIdx.x) >> 5;
    int lane = threadIdx.x & 31;
    if (warp >= Nn) return;
    int i = warp;
    const uint2* H = (const uint2*)g_H16;
    int start = g_rowptr[i];
    int end = g_rowptr[i + 1];
    float4 acc = make_float4(0.f, 0.f, 0.f, 0.f);
    int p = start;
    for (; p + 8 <= end; p += 8) {
        uint2 r[8];
#pragma unroll
        for (int q = 0; q < 8; q++) r[q] = H[g_csrc[p + q] * 32 + lane];
#pragma unroll
        for (int q = 0; q < 8; q++) {
            float2 a = __half22float2(*(__half2*)&r[q].x);
            float2 bvl = __half22float2(*(__half2*)&r[q].y);
            acc.x += a.x; acc.y += a.y; acc.z += bvl.x; acc.w += bvl.y;
        }
    }
    for (; p + 4 <= end; p += 4) {
        uint2 r[4];
#pragma unroll
        for (int q = 0; q < 4; q++) r[q] = H[g_csrc[p + q] * 32 + lane];
#pragma unroll
        for (int q = 0; q < 4; q++) {
            float2 a = __half22float2(*(__half2*)&r[q].x);
            float2 bvl = __half22float2(*(__half2*)&r[q].y);
            acc.x += a.x; acc.y += a.y; acc.z += bvl.x; acc.w += bvl.y;
        }
    }
    for (; p < end; p++) {
        uint2 r0 = H[g_csrc[p] * 32 + lane];
        float2 a = __half22float2(*(__half2*)&r0.x);
        float2 bvl = __half22float2(*(__half2*)&r0.y);
        acc.x += a.x; acc.y += a.y; acc.z += bvl.x; acc.w += bvl.y;
    }
    uint2 ri = H[i * 32 + lane];
    float2 ai = __half22float2(*(__half2*)&ri.x);
    float2 bi = __half22float2(*(__half2*)&ri.y);
    float el = 1.0f + eps[l];
    float4 o;
    o.x = fmaf(el, ai.x, acc.x);
    o.y = fmaf(el, ai.y, acc.y);
    o.z = fmaf(el, bi.x, acc.z);
    o.w = fmaf(el, bi.y, acc.w);
    *(float4*)(AGG + (long)i * Hh + lane * 4) = o;
}

// ---------------- tensor-core GEMM (R11 shape: 256 thr, 8 warps 32x32) ------
__global__ __launch_bounds__(256, 2) void k_gemm_tc(const float* __restrict__ A,
                                                    int widx,
                                                    const float* __restrict__ bias,
                                                    int usePre,
                                                    float* __restrict__ OutF,
                                                    __half* __restrict__ OutH,
                                                    const float* __restrict__ gamma,
                                                    const float* __restrict__ beta,
                                                    int slot) {
    extern __shared__ __align__(16) char smem[];
    char* Ahi = smem;
    char* Alo = smem + A_TILE;
    char* Bhi = smem + 2 * A_TILE;
    char* Blo = smem + 2 * A_TILE + B_TILE;

    int tid = threadIdx.x;
    int wid = tid >> 5;
    int lane = tid & 31;
    int row0 = blockIdx.x * 64;

    const __nv_bfloat16* WH = g_Whi + (long)widx * Hh * Hh;
    const __nv_bfloat16* WL = g_Wlo + (long)widx * Hh * Hh;
#pragma unroll
    for (int it = 0; it < 8; it++) {
        int idx = it * 256 + tid;
        int n = idx >> 4;
        int k0 = (idx & 15) * 8;
        uint32_t off = (uint32_t)n * RSTRIDE + k0 * 2;
        *(uint4*)(Bhi + off) = *(const uint4*)(WH + n * Hh + k0);
        *(uint4*)(Blo + off) = *(const uint4*)(WL + n * Hh + k0);
    }

#pragma unroll
    for (int it = 0; it < 8; it++) {
        int idx = it * 256 + tid;
        int row = idx >> 5;
        int c4 = idx & 31;
        int k0 = c4 * 4;
        int gr = row0 + row;
        float4 v = make_float4(0.f, 0.f, 0.f, 0.f);
        if (gr < Nn) {
            v = *(const float4*)(A + (long)gr * Hh + k0);
            if (usePre) {
                float4 s4 = *(const float4*)(g_s + k0);
                float4 t4 = *(const float4*)(g_t + k0);
                v.x = fmaxf(fmaf(s4.x, v.x, t4.x), 0.f);
                v.y = fmaxf(fmaf(s4.y, v.y, t4.y), 0.f);
                v.z = fmaxf(fmaf(s4.z, v.z, t4.z), 0.f);
                v.w = fmaxf(fmaf(s4.w, v.w, t4.w), 0.f);
            }
        }
        __nv_bfloat162 h01 = __floats2bfloat162_rn(v.x, v.y);
        __nv_bfloat162 h23 = __floats2bfloat162_rn(v.z, v.w);
        __nv_bfloat162 l01 = __floats2bfloat162_rn(v.x - __bfloat162float(h01.x),
                                                   v.y - __bfloat162float(h01.y));
        __nv_bfloat162 l23 = __floats2bfloat162_rn(v.z - __bfloat162float(h23.x),
                                                   v.w - __bfloat162float(h23.y));
        uint32_t off = (uint32_t)row * RSTRIDE + k0 * 2;
        *(uint2*)(Ahi + off) = make_uint2(*(uint32_t*)&h01, *(uint32_t*)&h23);
        *(uint2*)(Alo + off) = make_uint2(*(uint32_t*)&l01, *(uint32_t*)&l23);
    }
    __syncthreads();

    int wr = wid >> 2;
    int wc = wid & 3;
    int mrow0 = wr * 32;
    int ncol0 = wc * 32;

    float acc[2][4][4];
#pragma unroll
    for (int mb = 0; mb < 2; mb++)
#pragma unroll
        for (int nb = 0; nb < 4; nb++)
#pragma unroll
            for (int q = 0; q < 4; q++) acc[mb][nb][q] = 0.f;

    uint32_t aBaseH = smem_u32(Ahi);
    uint32_t aBaseL = smem_u32(Alo);
    uint32_t bBaseH = smem_u32(Bhi);
    uint32_t bBaseL = smem_u32(Blo);

    int aRow = mrow0 + (lane & 15);
    int aK = (lane >> 4) * 8;
    int bRow = ncol0 + (lane & 7) + ((lane >> 4) << 3);
    int bK = ((lane >> 3) & 1) * 8;

#pragma unroll
    for (int k0 = 0; k0 < 128; k0 += 16) {
        uint32_t ah[2][4], al[2][4];
#pragma unroll
        for (int mb = 0; mb < 2; mb++) {
            uint32_t ao = (uint32_t)(aRow + mb * 16) * RSTRIDE + (uint32_t)(k0 + aK) * 2;
            LDMATRIX_X4(ah[mb][0], ah[mb][1], ah[mb][2], ah[mb][3], aBaseH + ao);
            LDMATRIX_X4(al[mb][0], al[mb][1], al[mb][2], al[mb][3], aBaseL + ao);
        }
        uint32_t bh[4][2], bl[4][2];
#pragma unroll
        for (int np = 0; np < 2; np++) {
            uint32_t bo = (uint32_t)(bRow + np * 16) * RSTRIDE + (uint32_t)(k0 + bK) * 2;
            uint32_t r0, r1, r2, r3;
            LDMATRIX_X4(r0, r1, r2, r3, bBaseH + bo);
            bh[np * 2][0] = r0; bh[np * 2][1] = r1;
            bh[np * 2 + 1][0] = r2; bh[np * 2 + 1][1] = r3;
            LDMATRIX_X4(r0, r1, r2, r3, bBaseL + bo);
            bl[np * 2][0] = r0; bl[np * 2][1] = r1;
            bl[np * 2 + 1][0] = r2; bl[np * 2 + 1][1] = r3;
        }
#pragma unroll
        for (int mb = 0; mb < 2; mb++)
#pragma unroll
            for (int nb = 0; nb < 4; nb++) {
                MMA_BF16(acc[mb][nb], ah[mb], bh[nb]);
                MMA_BF16(acc[mb][nb], ah[mb], bl[nb]);
                MMA_BF16(acc[mb][nb], al[mb], bh[nb]);
            }
    }

    int cbase = ncol0 + (lane & 3) * 2;
    float2 bi[4];
#pragma unroll
    for (int nb = 0; nb < 4; nb++) bi[nb] = *(const float2*)(bias + cbase + nb * 8);

    float psS[4][2], psQ[4][2];
#pragma unroll
    for (int nb = 0; nb < 4; nb++) {
        psS[nb][0] = 0.f; psS[nb][1] = 0.f;
        psQ[nb][0] = 0.f; psQ[nb][1] = 0.f;
    }
#pragma unroll
    for (int mb = 0; mb < 2; mb++)
#pragma unroll
        for (int h = 0; h < 2; h++) {
            int m = row0 + mrow0 + mb * 16 + h * 8 + (lane >> 2);
            if (m < Nn) {
#pragma unroll
                for (int nb = 0; nb < 4; nb++) {
                    float v0 = acc[mb][nb][h * 2 + 0] + bi[nb].x;
                    float v1 = acc[mb][nb][h * 2 + 1] + bi[nb].y;
                    if (OutH) {
                        __half2 hh = __floats2half2_rn(v0, v1);
                        *(uint32_t*)(OutH + (long)m * Hh + cbase + nb * 8) = *(uint32_t*)&hh;
                    } else {
                        *(float2*)(OutF + (long)m * Hh + cbase + nb * 8) = make_float2(v0, v1);
                    }
                    psS[nb][0] += v0; psQ[nb][0] += v0 * v0;
                    psS[nb][1] += v1; psQ[nb][1] += v1 * v1;
                }
            }
        }
#pragma unroll
    for (int nb = 0; nb < 4; nb++)
#pragma unroll
        for (int j = 0; j < 2; j++) {
            float s = psS[nb][j], q = psQ[nb][j];
            s += __shfl_xor_sync(0xffffffffu, s, 4);
            q += __shfl_xor_sync(0xffffffffu, q, 4);
            s += __shfl_xor_sync(0xffffffffu, s, 8);
            q += __shfl_xor_sync(0xffffffffu, q, 8);
            s += __shfl_xor_sync(0xffffffffu, s, 16);
            q += __shfl_xor_sync(0xffffffffu, q, 16);
            if ((lane >> 2) == 0) {
                atomicAdd(&g_colS[cbase + nb * 8 + j], s);
                atomicAdd(&g_colQ[cbase + nb * 8 + j], q);
            }
        }
    bn_finalize_tail(tid, gridDim.x, gamma, beta, slot);
}

// ---------------- final: pool(relu(bn(z16))) + classifier + self-clean ------
__global__ void k_postpool(const int* __restrict__ batch,
                           const float* __restrict__ clsW,
                           const float* __restrict__ clsb,
                           float* __restrict__ out) {
    int idx = blockIdx.x * blockDim.x + threadIdx.x;
    int tid = threadIdx.x;
    if (idx < Nn * Hh / 4) {
        int i = idx >> 5;
        int c = idx & 31;
        uint2 r = ((const uint2*)g_H16)[idx];
        float2 f0 = __half22float2(*(__half2*)&r.x);
        float2 f1 = __half22float2(*(__half2*)&r.y);
        float4 s4 = ((const float4*)g_s)[c];
        float4 t4 = ((const float4*)g_t)[c];
        float4 v;
        v.x = fmaxf(fmaf(s4.x, f0.x, t4.x), 0.f);
        v.y = fmaxf(fmaf(s4.y, f0.y, t4.y), 0.f);
        v.z = fmaxf(fmaf(s4.z, f1.x, t4.z), 0.f);
        v.w = fmaxf(fmaf(s4.w, f1.y, t4.w), 0.f);
        int g = batch[i];
        float* p = g_pool + (long)g * Hh + c * 4;
        asm volatile("red.global.add.v4.f32 [%0], {%1,%2,%3,%4};"
                     :: "l"(p), "f"(v.x), "f"(v.y), "f"(v.z), "f"(v.w)
                     : "memory");
        if (c == 0) atomicAdd(&g_cnt[g], 1.0f);
    }
    if (tid < 8) {
        int z = blockIdx.x * 8 + tid;
        if (z < Nn) { g_deg[z] = 0; g_sx[z] = 0.f; }
    }
    __threadfence();
    __syncthreads();
    __shared__ int isLast;
    if (tid == 0)
        isLast = (atomicAdd(&g_ctr[7], 1u) == (unsigned)(gridDim.x - 1)) ? 1 : 0;
    __syncthreads();
    if (isLast) {
        __threadfence();
        if (tid < Gg * Cc) {
            int g = tid >> 1;
            int cc = tid & 1;
            float inv = 1.0f / fmaxf(((volatile float*)g_cnt)[g], 1.0f);
            float acc = clsb[cc];
#pragma unroll 8
            for (int j = 0; j < Hh; j++)
                acc += ((volatile float*)g_pool)[g * Hh + j] * inv * clsW[j * Cc + cc];
            out[g * Cc + cc] = acc;
        }
        __syncthreads();
        for (int q = tid; q < Gg * Hh; q += blockDim.x) g_pool[q] = 0.f;
        if (tid < Gg) g_cnt[tid] = 0.f;
        if (tid < 8) g_ctr[tid] = 0u;
    }
}

// ---------------- launch ----------------------------------------------------
extern "C" void kernel_launch(void* const* d_in, const int* in_sizes, int n_in,
                              void* d_out, int out_size) {
    const float* x    = (const float*)d_in[0];
    const int*   ei   = (const int*)d_in[1];
    const int*   batch= (const int*)d_in[2];
    const float* encW = (const float*)d_in[3];
    const float* encb = (const float*)d_in[4];
    const float* W1   = (const float*)d_in[5];
    const float* b1   = (const float*)d_in[6];
    const float* g1   = (const float*)d_in[7];
    const float* be1  = (const float*)d_in[8];
    const float* W2   = (const float*)d_in[9];
    const float* b2   = (const float*)d_in[10];
    const float* eps  = (const float*)d_in[11];
    const float* bng  = (const float*)d_in[12];
    const float* bnb  = (const float*)d_in[13];
    const float* clsW = (const float*)d_in[14];
    const float* clsb = (const float*)d_in[15];
    float* out = (float*)d_out;

    float *pY = nullptr, *pAGG = nullptr;
    __half* pH = nullptr;
    cudaGetSymbolAddress((void**)&pY, g_Y);
    cudaGetSymbolAddress((void**)&pAGG, g_AGG);
    cudaGetSymbolAddress((void**)&pH, g_H16);

    static int smemSet = 0;
    if (!smemSet) {
        cudaFuncSetAttribute(k_gemm_tc, cudaFuncAttributeMaxDynamicSharedMemorySize, SMEM_DYN);
        smemSet = 1;
    }

    const int elemBlocks = (Nn * Hh / 4) / 256;          // 2500
    const int gemmBlocks = (Nn + 63) / 64;               // 313
    const int gathBlocks = (Nn + 7) / 8;                 // 2500

    k_prep_all<<<EDGE4_BLOCKS + WPREP_BLOCKS + 1, 256>>>(ei, x, W1, W2, encW, encb);
    k_scan<<<1, 1024>>>();
    k_fill_l1<<<EDGE4_BLOCKS + L1_BLOCKS, 256>>>(ei, x, b1, eps, g1, be1);

    // layer 0: gemm2 -> fp32 raw Z into g_AGG (stats slot 1)
    k_gemm_tc<<<gemmBlocks, 256, SMEM_DYN>>>(pY, 0, b2, 1, pAGG, nullptr, bng, bnb, 1);

    for (int l = 1; l < Ll; l++) {
        // pre-activate previous layer's Z into fp16 gather operand
        k_tohalf<<<elemBlocks, 256>>>(pAGG);
        k_gather<<<gathBlocks, 256>>>(pAGG, eps, l);
        k_gemm_tc<<<gemmBlocks, 256, SMEM_DYN>>>(pAGG, 2 * l - 1, b1 + l * Hh, 0,
                                                 pY, nullptr, g1 + l * Hh, be1 + l * Hh, 2 * l);
        if (l < Ll - 1) {
            // mid layer: raw Z fp32 for next tohalf
            k_gemm_tc<<<gemmBlocks, 256, SMEM_DYN>>>(pY, 2 * l, b2 + l * Hh, 1,
                                                     pAGG, nullptr, bng + l * Hh, bnb + l * Hh, 2 * l + 1);
        } else {
            // last layer: raw Z fp16 for postpool
            k_gemm_tc<<<gemmBlocks, 256, SMEM_DYN>>>(pY, 2 * l, b2 + l * Hh, 1,
                                                     nullptr, pH, bng + l * Hh, bnb + l * Hh, 2 * l + 1);
        }
    }

    k_postpool<<<elemBlocks, 256>>>(batch, clsW, clsb, out);
}